// round 3
// baseline (speedup 1.0000x reference)
#include <cuda_runtime.h>
#include <cuda_bf16.h>
#include <cstdint>

// ---------------------------------------------------------------------------
// Speculative-decode cache-loc compaction.
//   span[b]      = accept_length[b] + 1
//   old_start[b] = exclusive_cumsum(span)[b]
//   new_start[b] = exclusive_cumsum(accept_length_filter)[b]
//   out[new_start[b] + i] = tgt_cache_loc[old_start[b] + i],  i < filter[b]
//
// Inputs (metadata order):
//   d_in[0] : float32 tgt_cache_loc [tgt_len]
//   d_in[1] : int32   accept_length [B]
//   d_in[2] : int32   accept_length_filter [B]
//   d_in[3] : int32   out_size (scalar)
// Output: float32 [out_size]
// ---------------------------------------------------------------------------

#define CHUNK 256
#define MAXB (1 << 17)
#define MAXNBLK 1024

__device__ int g_span_boff[MAXNBLK];   // partial sums, then exclusive offsets
__device__ int g_filt_boff[MAXNBLK];
__device__ int g_old_start[MAXB];
__device__ int g_new_start[MAXB];

// Full-warp inclusive scan (ALL 32 lanes must call this).
__device__ __forceinline__ int warp_incl_scan(int v, int lane) {
    #pragma unroll
    for (int off = 1; off < 32; off <<= 1) {
        int n = __shfl_up_sync(0xFFFFFFFFu, v, off);
        if (lane >= off) v += n;
    }
    return v;
}

// ---- kernel 1: per-chunk partial sums -------------------------------------
__global__ void __launch_bounds__(CHUNK)
k_partial_sums(const int* __restrict__ al,
               const int* __restrict__ alf, int B) {
    int tid = threadIdx.x;
    int i = blockIdx.x * CHUNK + tid;
    int s = 0, f = 0;
    if (i < B) { s = al[i] + 1; f = alf[i]; }

    #pragma unroll
    for (int off = 16; off > 0; off >>= 1) {
        s += __shfl_down_sync(0xFFFFFFFFu, s, off);
        f += __shfl_down_sync(0xFFFFFFFFu, f, off);
    }
    __shared__ int ws[CHUNK / 32], wf[CHUNK / 32];
    int wid = tid >> 5, lane = tid & 31;
    if (lane == 0) { ws[wid] = s; wf[wid] = f; }
    __syncthreads();
    if (wid == 0) {
        int vs = (lane < CHUNK / 32) ? ws[lane] : 0;
        int vf = (lane < CHUNK / 32) ? wf[lane] : 0;
        #pragma unroll
        for (int off = 16; off > 0; off >>= 1) {
            vs += __shfl_down_sync(0xFFFFFFFFu, vs, off);
            vf += __shfl_down_sync(0xFFFFFFFFu, vf, off);
        }
        if (lane == 0) {
            g_span_boff[blockIdx.x] = vs;
            g_filt_boff[blockIdx.x] = vf;
        }
    }
}

// ---- kernel 2: exclusive scan of block sums (single block, 1 elem/thread) --
__global__ void __launch_bounds__(MAXNBLK)
k_scan_bsums(int nblk) {
    __shared__ int ss[MAXNBLK], sf[MAXNBLK];
    int t = threadIdx.x;
    ss[t] = (t < nblk) ? g_span_boff[t] : 0;
    sf[t] = (t < nblk) ? g_filt_boff[t] : 0;
    __syncthreads();
    #pragma unroll
    for (int off = 1; off < MAXNBLK; off <<= 1) {
        int vs = (t >= off) ? ss[t - off] : 0;
        int vf = (t >= off) ? sf[t - off] : 0;
        __syncthreads();
        ss[t] += vs;
        sf[t] += vf;
        __syncthreads();
    }
    if (t < nblk) {
        g_span_boff[t] = (t == 0) ? 0 : ss[t - 1];
        g_filt_boff[t] = (t == 0) ? 0 : sf[t - 1];
    }
}

// ---- kernel 3: full exclusive starts per batch ----------------------------
__global__ void __launch_bounds__(CHUNK)
k_write_starts(const int* __restrict__ al,
               const int* __restrict__ alf, int B) {
    int tid = threadIdx.x;
    int i = blockIdx.x * CHUNK + tid;
    int s = 0, f = 0;
    if (i < B) { s = al[i] + 1; f = alf[i]; }

    int wid = tid >> 5, lane = tid & 31;
    int incl_s = warp_incl_scan(s, lane);
    int incl_f = warp_incl_scan(f, lane);

    __shared__ int ws[CHUNK / 32], wf[CHUNK / 32];
    __shared__ int wso[CHUNK / 32], wfo[CHUNK / 32];
    if (lane == 31) { ws[wid] = incl_s; wf[wid] = incl_f; }
    __syncthreads();
    if (wid == 0) {
        // ALL 32 lanes participate in the shuffle scan (R0 deadlock fix).
        int vs = (lane < CHUNK / 32) ? ws[lane] : 0;
        int vf = (lane < CHUNK / 32) ? wf[lane] : 0;
        int is  = warp_incl_scan(vs, lane);
        int iff = warp_incl_scan(vf, lane);
        if (lane < CHUNK / 32) {
            wso[lane] = is - vs;    // exclusive warp offset within block
            wfo[lane] = iff - vf;
        }
    }
    __syncthreads();

    if (i < B) {
        g_old_start[i] = incl_s - s + wso[wid] + g_span_boff[blockIdx.x];
        g_new_start[i] = incl_f - f + wfo[wid] + g_filt_boff[blockIdx.x];
    }
}

// ---- kernel 4: the copy (one warp per batch) ------------------------------
__global__ void __launch_bounds__(256)
k_copy(const float* __restrict__ src,
       const int* __restrict__ alf,
       float* __restrict__ out, int B) {
    int gwarp = (blockIdx.x * blockDim.x + threadIdx.x) >> 5;
    int lane = threadIdx.x & 31;
    if (gwarp >= B) return;
    int len = alf[gwarp];            // warp-uniform broadcast load
    if (len == 0) return;
    int os = g_old_start[gwarp];
    int ns = g_new_start[gwarp];
    for (int i = lane; i < len; i += 32)
        out[ns + i] = __ldg(&src[os + i]);
}

// ---------------------------------------------------------------------------
extern "C" void kernel_launch(void* const* d_in, const int* in_sizes, int n_in,
                              void* d_out, int out_size) {
    const float* tgt = (const float*)d_in[0];
    const int* al  = (const int*)d_in[1];
    const int* alf = (const int*)d_in[2];
    float* out = (float*)d_out;

    int B = in_sizes[1];
    int nblk = (B + CHUNK - 1) / CHUNK;   // 256 for B=65536

    k_partial_sums<<<nblk, CHUNK>>>(al, alf, B);
    k_scan_bsums<<<1, MAXNBLK>>>(nblk);
    k_write_starts<<<nblk, CHUNK>>>(al, alf, B);

    long long total_threads = (long long)B * 32;
    int tpb = 256;
    int cblocks = (int)((total_threads + tpb - 1) / tpb);
    k_copy<<<cblocks, tpb>>>(tgt, alf, out, B);
}